// round 13
// baseline (speedup 1.0000x reference)
#include <cuda_runtime.h>
#include <cuda_fp16.h>
#include <cstdint>

typedef unsigned long long u64;

namespace {
constexpr int B_ = 256, T_ = 128, SD_ = 8, AD_ = 2, H_ = 3, K_ = 4, HID_ = 256;
constexpr int QD_ = SD_ + AD_;    // 10
constexpr int HK_ = H_ * K_;      // 12
constexpr int FEAT_ = HK_ + QD_;  // 22
constexpr int MT_ = 128;          // tokens per CTA = one batch
constexpr int KP_ = 64;           // main-GEMM K panel
constexpr int ASTRIDE = 264;      // fp16 elems per A row (256 + 8 pad) -> 528B
}

// pre-converted fp16 weights (single term each)
__device__ __half g_W2h[HID_ * HID_];
__device__ __half g_W1h[HID_ * 32];     // [256][32], cols 22..31 zero

// ---------------- helpers ----------------
__device__ __forceinline__ uint32_t smem_u32(const void* p) {
    uint32_t a;
    asm("{ .reg .u64 t; cvta.to.shared.u64 t, %1; cvt.u32.u64 %0, t; }" : "=r"(a) : "l"(p));
    return a;
}
__device__ __forceinline__ void ldsm4(uint32_t r[4], uint32_t addr) {
    asm volatile("ldmatrix.sync.aligned.m8n8.x4.shared.b16 {%0,%1,%2,%3}, [%4];"
                 : "=r"(r[0]), "=r"(r[1]), "=r"(r[2]), "=r"(r[3]) : "r"(addr));
}
__device__ __forceinline__ void mma16816(float c[4], const uint32_t a[4],
                                         uint32_t b0, uint32_t b1) {
    asm volatile(
        "mma.sync.aligned.m16n8k16.row.col.f32.f16.f16.f32 "
        "{%0,%1,%2,%3}, {%4,%5,%6,%7}, {%8,%9}, {%0,%1,%2,%3};"
        : "+f"(c[0]), "+f"(c[1]), "+f"(c[2]), "+f"(c[3])
        : "r"(a[0]), "r"(a[1]), "r"(a[2]), "r"(a[3]), "r"(b0), "r"(b1));
}
__device__ __forceinline__ void cp_async16(uint32_t dst, const void* src) {
    asm volatile("cp.async.ca.shared.global [%0], [%1], 16;" :: "r"(dst), "l"(src) : "memory");
}
__device__ __forceinline__ uint32_t pack_half2(float lo, float hi) {
    __half2 h = __floats2half2_rn(lo, hi);
    return *(uint32_t*)&h;
}

// ---------------------------------------------------------------------------
// Prep: W2 -> fp16 (vectorized); first 512 threads also convert W1 (pad 22->32).
// ---------------------------------------------------------------------------
__global__ __launch_bounds__(256) void wsplit_kernel(const float* __restrict__ W2,
                                                     const float* __restrict__ W1) {
    const int gid = blockIdx.x * 256 + threadIdx.x;   // 16384 threads
    {
        const float4 w4 = ((const float4*)W2)[gid];
        ((__half2*)g_W2h)[gid * 2]     = __floats2half2_rn(w4.x, w4.y);
        ((__half2*)g_W2h)[gid * 2 + 1] = __floats2half2_rn(w4.z, w4.w);
    }
    if (gid < 512) {  // W1: 8192 elements, 16 per thread
#pragma unroll
        for (int j = 0; j < 16; j++) {
            const int i = gid * 16 + j;
            const int n = i >> 5, k = i & 31;
            g_W1h[i] = __float2half_rn((k < FEAT_) ? W1[n * FEAT_ + k] : 0.f);
        }
    }
}

// ---------------------------------------------------------------------------
// Fused kernel: one CTA = one batch (128 tokens), 256 threads, 8 warps.
//   prologue: cp.async ALL 4 B panels (full fp16 W2, 128 KB) + W1 tile.
//   phase 0: attention (2-way jj split), feat written as single fp16 tile.
//   phase 1: h1 via HMMA (single term, K=32), relu(D+b1) -> fp16 -> A tile.
//   phase 2: main HMMA D = A @ fp16(W2)^T — ALL B resident, NO barriers,
//            16 straight ks iterations of 8 ldsm + 32 MMA.
//   epilogue: h2 = D + b2; relu; dot Wout; reduce; +bout.
// ---------------------------------------------------------------------------
__global__ __launch_bounds__(256) void fused_kernel(
    const float* __restrict__ state, const float* __restrict__ action,
    const float* __restrict__ Wk, const float* __restrict__ Wq,
    const float* __restrict__ Wv,
    const float* __restrict__ b1, const float* __restrict__ b2,
    const float* __restrict__ Wout, const float* __restrict__ bout,
    float* __restrict__ out)
{
    extern __shared__ char smem[];
    constexpr int ABYTES = MT_ * ASTRIDE * 2;          // 67584
    constexpr int OFF_A  = 0;
    constexpr int OFF_B  = ABYTES;                     // 4 panels x 32768 = 131072
    constexpr int BPANEL = HID_ * KP_ * 2;             // 32768
    constexpr int OFF_W1T = OFF_B + 4 * BPANEL;        // 16384 (single fp16)
    constexpr int OFF_FH  = OFF_W1T + 16384;           // feat [128][64B] = 8192
    constexpr int OFF_BW  = OFF_FH + 8192;             // float2 x 256 = 2048
    constexpr int OFF_B1  = OFF_BW + 2048;             // float x 256
    constexpr int OFF_RED = OFF_B1 + 1024;             // float x 128
    // aliases inside A region (dead until phase 1 writes A)
    constexpr int OFF_SK = 0, OFF_SV = 6144, OFF_PART = 12288;

    const uint32_t sb = smem_u32(smem);
    const int tid = threadIdx.x, wid = tid >> 5, ln = tid & 31;
    const int b = blockIdx.x;

    float2* sBW = (float2*)(smem + OFF_BW);
    float* sB1 = (float*)(smem + OFF_B1);
    float* sred = (float*)(smem + OFF_RED);
    float (*sK)[HK_] = (float(*)[HK_])(smem + OFF_SK);
    float (*sV)[HK_] = (float(*)[HK_])(smem + OFF_SV);
    float (*sPA)[MT_] = (float(*)[MT_])(smem + OFF_PART);

    // ---- prologue: stage ALL 4 B panels + W1 tile via cp.async ----
    {
        const int srow0 = tid >> 3, sc = tid & 7;
        const int scx = (sc ^ (srow0 & 7)) << 4;       // row&7 constant across j
#pragma unroll
        for (int p = 0; p < 4; p++) {
            const uint32_t dbase = sb + OFF_B + (uint32_t)(p * BPANEL + scx);
            const int goff = srow0 * HID_ + p * KP_ + sc * 8;
#pragma unroll
            for (int j = 0; j < 8; j++) {
                cp_async16(dbase + (uint32_t)((srow0 + j * 32) * 128),
                           g_W2h + goff + j * 32 * HID_);
            }
            asm volatile("cp.async.commit_group;" ::: "memory");
        }
        // W1 tile (64B rows, chunk c ^= (row>>1)&3)
        for (int it = tid; it < 1024; it += 256) {
            const int row = it >> 2, c = it & 3;
            const uint32_t dst = sb + OFF_W1T + (uint32_t)(row * 64 +
                                                           ((c ^ ((row >> 1) & 3)) << 4));
            cp_async16(dst, g_W1h + row * 32 + c * 8);
        }
        asm volatile("cp.async.commit_group;" ::: "memory");
    }

    // zero feat tile (pad cols 22..31 stay 0): 8192 B = 512 float4
    {
        float4* z = (float4*)(smem + OFF_FH);
#pragma unroll
        for (int i = 0; i < 2; i++) z[tid + i * 256] = make_float4(0.f, 0.f, 0.f, 0.f);
    }
    sBW[tid] = make_float2(b2[tid], Wout[tid]);
    sB1[tid] = b1[tid];
    if (tid < MT_) sred[tid] = 0.f;

    // ---- phase 0: attention ----
    const int half = tid >> 7, t = tid & 127;
    float qs[QD_], q[HK_], kp[HK_], vp[HK_];
    {
        const float* st = state + (size_t)(b * T_ + t) * SD_;
        const float* ac = action + (size_t)(b * T_ + t) * AD_;
#pragma unroll
        for (int c = 0; c < SD_; c++) qs[c] = st[c];
        qs[SD_] = ac[0];
        qs[SD_ + 1] = ac[1];
#pragma unroll
        for (int i = 0; i < HK_; i++) {
            float a = 0.f;
#pragma unroll
            for (int c = 0; c < QD_; c++) a = fmaf(qs[c], Wq[i * QD_ + c], a);
            q[i] = a;
        }
#pragma unroll
        for (int i = 0; i < HK_; i++) {
            float ak = 0.f, av = 0.f;
#pragma unroll
            for (int c = 0; c < K_; c++) {
                ak = fmaf(qs[c], Wk[i * K_ + c], ak);
                av = fmaf(qs[c], Wv[i * K_ + c], av);
            }
            kp[i] = ak; vp[i] = av;
        }
        if (half == 0) {
#pragma unroll
            for (int i = 0; i < HK_; i++) { sK[t][i] = kp[i]; sV[t][i] = vp[i]; }
        }
    }
    __syncthreads();

    {
        float sum0 = 0.f, sum1 = 0.f, sum2 = 0.f;
        float acc[HK_];
#pragma unroll
        for (int i = 0; i < HK_; i++) acc[i] = 0.f;
        const int j0 = half * 64;
#pragma unroll 4
        for (int jx = 0; jx < 64; jx++) {
            const int jj = j0 + jx;
            const float4 k0 = *(const float4*)&sK[jj][0];
            const float4 k1 = *(const float4*)&sK[jj][4];
            const float4 k2 = *(const float4*)&sK[jj][8];
            float s0 = q[0]*k0.x + q[1]*k0.y + q[2]*k0.z + q[3]*k0.w;
            float s1 = q[4]*k1.x + q[5]*k1.y + q[6]*k1.z + q[7]*k1.w;
            float s2 = q[8]*k2.x + q[9]*k2.y + q[10]*k2.z + q[11]*k2.w;
            const float e0 = __expf(0.5f * s0);
            const float e1 = __expf(0.5f * s1);
            const float e2 = __expf(0.5f * s2);
            sum0 += e0; sum1 += e1; sum2 += e2;
            const float4 v0 = *(const float4*)&sV[jj][0];
            const float4 v1 = *(const float4*)&sV[jj][4];
            const float4 v2 = *(const float4*)&sV[jj][8];
            acc[0]  = fmaf(e0, v0.x, acc[0]);  acc[1]  = fmaf(e0, v0.y, acc[1]);
            acc[2]  = fmaf(e0, v0.z, acc[2]);  acc[3]  = fmaf(e0, v0.w, acc[3]);
            acc[4]  = fmaf(e1, v1.x, acc[4]);  acc[5]  = fmaf(e1, v1.y, acc[5]);
            acc[6]  = fmaf(e1, v1.z, acc[6]);  acc[7]  = fmaf(e1, v1.w, acc[7]);
            acc[8]  = fmaf(e2, v2.x, acc[8]);  acc[9]  = fmaf(e2, v2.y, acc[9]);
            acc[10] = fmaf(e2, v2.z, acc[10]); acc[11] = fmaf(e2, v2.w, acc[11]);
        }
        if (half == 1) {
            sPA[0][t] = sum0; sPA[1][t] = sum1; sPA[2][t] = sum2;
#pragma unroll
            for (int i = 0; i < HK_; i++) sPA[3 + i][t] = acc[i];
        }
        __syncthreads();
        if (half == 0) {
            sum0 += sPA[0][t]; sum1 += sPA[1][t]; sum2 += sPA[2][t];
#pragma unroll
            for (int i = 0; i < HK_; i++) acc[i] += sPA[3 + i][t];
            float s0 = q[0]*kp[0] + q[1]*kp[1] + q[2]*kp[2] + q[3]*kp[3];
            float s1 = q[4]*kp[4] + q[5]*kp[5] + q[6]*kp[6] + q[7]*kp[7];
            float s2 = q[8]*kp[8] + q[9]*kp[9] + q[10]*kp[10] + q[11]*kp[11];
            const float e0 = __expf(0.5f * s0);
            const float e1 = __expf(0.5f * s1);
            const float e2 = __expf(0.5f * s2);
            sum0 -= e0; sum1 -= e1; sum2 -= e2;
            const float i0 = 1.f / sum0, i1 = 1.f / sum1, i2 = 1.f / sum2;
            float f[FEAT_];
#pragma unroll
            for (int k = 0; k < K_; k++) {
                f[k]     = fmaf(-e0, vp[k],     acc[k])     * i0 - vp[k];
                f[4 + k] = fmaf(-e1, vp[4 + k], acc[4 + k]) * i1 - vp[4 + k];
                f[8 + k] = fmaf(-e2, vp[8 + k], acc[8 + k]) * i2 - vp[8 + k];
            }
#pragma unroll
            for (int c = 0; c < QD_; c++) f[HK_ + c] = qs[c];
            // write feat as single fp16 into swizzled [128][32] tile
#pragma unroll
            for (int c = 0; c < FEAT_; c++) {
                const uint32_t ad = (uint32_t)(t * 64 + (((c >> 3) ^ ((t >> 1) & 3)) << 4) +
                                               (c & 7) * 2);
                *(__half*)(smem + OFF_FH + ad) = __float2half_rn(f[c]);
            }
        }
    }
    asm volatile("cp.async.wait_group 0;" ::: "memory");  // B panels + W1 all resident
    __syncthreads();

    // ---- warp tiling: 2(M) x 4(N), warp tile 64x64 ----
    const int mwarp = wid >> 2, nwarp = wid & 3;
    const int m0w = mwarp * 64, n0w = nwarp * 64;
    const int rsel = (ln & 7) | (((ln >> 4) & 1) << 3);
    const int cpart = (ln >> 3) & 1;

    float acc[4][8][4];
#pragma unroll
    for (int i = 0; i < 4; i++)
#pragma unroll
        for (int j = 0; j < 8; j++)
#pragma unroll
            for (int c = 0; c < 4; c++) acc[i][j][c] = 0.f;

    // ---- phase 1: W1 HMMA (single term, K=32) ----
    {
        const int aRow = m0w + (ln & 15);
        const int aSw = (aRow >> 1) & 3;
        const int aCS = ln >> 4;
        const int bSw = (rsel >> 1) & 3;
#pragma unroll
        for (int ks = 0; ks < 2; ks++) {
            uint32_t ah[4][4], bh[4][4];
#pragma unroll
            for (int i = 0; i < 4; i++)
                ldsm4(ah[i], sb + OFF_FH + (uint32_t)((aRow + i * 16) * 64 +
                              (((ks * 2 + aCS) ^ aSw) << 4)));
#pragma unroll
            for (int j = 0; j < 4; j++)
                ldsm4(bh[j], sb + OFF_W1T + (uint32_t)((n0w + j * 16 + rsel) * 64 +
                              (((ks * 2 + cpart) ^ bSw) << 4)));
#pragma unroll
            for (int j = 0; j < 4; j++)
#pragma unroll
                for (int i = 0; i < 4; i++) {
                    mma16816(acc[i][2 * j],     ah[i], bh[j][0], bh[j][1]);
                    mma16816(acc[i][2 * j + 1], ah[i], bh[j][2], bh[j][3]);
                }
        }
        // h1 = relu(D + b1) -> fp16 -> main A tile (row-major, padded stride)
#pragma unroll
        for (int i = 0; i < 4; i++) {
            const int r0 = m0w + i * 16 + (ln >> 2);
#pragma unroll
            for (int j = 0; j < 8; j++) {
                const int n = n0w + j * 8 + 2 * (ln & 3);
                const float h0 = fmaxf(acc[i][j][0] + sB1[n], 0.f);
                const float h1v = fmaxf(acc[i][j][1] + sB1[n + 1], 0.f);
                const float h2 = fmaxf(acc[i][j][2] + sB1[n], 0.f);
                const float h3 = fmaxf(acc[i][j][3] + sB1[n + 1], 0.f);
                *(uint32_t*)(smem + OFF_A + r0 * (ASTRIDE * 2) + n * 2) = pack_half2(h0, h1v);
                *(uint32_t*)(smem + OFF_A + (r0 + 8) * (ASTRIDE * 2) + n * 2) = pack_half2(h2, h3);
            }
        }
    }
    __syncthreads();

    // ---- phase 2: main HMMA GEMM — all B resident, barrier-free ----
#pragma unroll
    for (int i = 0; i < 4; i++)
#pragma unroll
        for (int j = 0; j < 8; j++)
#pragma unroll
            for (int c = 0; c < 4; c++) acc[i][j][c] = 0.f;

    const uint32_t aBase = sb + OFF_A +
        (uint32_t)((m0w + (ln & 15)) * (ASTRIDE * 2) + (ln >> 4) * 16);
    const int swz = ln & 7;
    const uint32_t bRowBase = sb + OFF_B + (uint32_t)((n0w + rsel) * 128);

#pragma unroll
    for (int kk = 0; kk < 16; kk++) {
        const int ks = kk & 3;
        uint32_t ah[4][4], bh[4][4];
        const uint32_t ka = (uint32_t)(kk * 32);
#pragma unroll
        for (int i = 0; i < 4; i++)
            ldsm4(ah[i], aBase + ka + (uint32_t)(i * 16 * ASTRIDE * 2));
        const uint32_t bBase = bRowBase + (uint32_t)((kk >> 2) * BPANEL) +
                               (uint32_t)(((ks * 2 + cpart) ^ swz) << 4);
#pragma unroll
        for (int jj = 0; jj < 4; jj++)
            ldsm4(bh[jj], bBase + (uint32_t)(jj * 16 * 128));
#pragma unroll
        for (int jj = 0; jj < 4; jj++)
#pragma unroll
            for (int i = 0; i < 4; i++) {
                mma16816(acc[i][2 * jj],     ah[i], bh[jj][0], bh[jj][1]);
                mma16816(acc[i][2 * jj + 1], ah[i], bh[jj][2], bh[jj][3]);
            }
    }

    // ---- epilogue: h2 = acc + b2; relu; dot Wout; reduce ----
    float po[4][2] = {{0.f, 0.f}, {0.f, 0.f}, {0.f, 0.f}, {0.f, 0.f}};
#pragma unroll
    for (int i = 0; i < 4; i++)
#pragma unroll
        for (int j = 0; j < 8; j++) {
            const int nb = n0w + j * 8 + 2 * (ln & 3);
            const float2 bw0 = sBW[nb], bw1 = sBW[nb + 1];
            po[i][0] += fmaxf(acc[i][j][0] + bw0.x, 0.f) * bw0.y
                      + fmaxf(acc[i][j][1] + bw1.x, 0.f) * bw1.y;
            po[i][1] += fmaxf(acc[i][j][2] + bw0.x, 0.f) * bw0.y
                      + fmaxf(acc[i][j][3] + bw1.x, 0.f) * bw1.y;
        }
#pragma unroll
    for (int o = 1; o <= 2; o <<= 1)
#pragma unroll
        for (int i = 0; i < 4; i++) {
            po[i][0] += __shfl_xor_sync(0xffffffffu, po[i][0], o);
            po[i][1] += __shfl_xor_sync(0xffffffffu, po[i][1], o);
        }
    if ((ln & 3) == 0) {
        const int r = ln >> 2;
#pragma unroll
        for (int i = 0; i < 4; i++) {
            atomicAdd(&sred[m0w + i * 16 + r], po[i][0]);
            atomicAdd(&sred[m0w + i * 16 + 8 + r], po[i][1]);
        }
    }
    __syncthreads();
    if (tid < MT_) out[b * T_ + tid] = sred[tid] + bout[0];
}

extern "C" void kernel_launch(void* const* d_in, const int* in_sizes, int n_in,
                              void* d_out, int out_size) {
    const float* state  = (const float*)d_in[0];
    const float* action = (const float*)d_in[1];
    const float* Wk     = (const float*)d_in[2];
    const float* Wq     = (const float*)d_in[3];
    const float* Wv     = (const float*)d_in[4];
    const float* W1     = (const float*)d_in[5];
    const float* b1     = (const float*)d_in[6];
    const float* W2     = (const float*)d_in[7];
    const float* b2     = (const float*)d_in[8];
    const float* Wout   = (const float*)d_in[9];
    const float* bout   = (const float*)d_in[10];
    float* out = (float*)d_out;

    const int smem = MT_ * ASTRIDE * 2          // A tile          67584
                   + 4 * (HID_ * KP_ * 2)       // B: full W2     131072
                   + 16384                      // W1 tile (fp16)
                   + 8192                       // feat tile (fp16)
                   + 2048 + 1024 + 512;         // bw, b1, red    -> 226816
    cudaFuncSetAttribute(fused_kernel, cudaFuncAttributeMaxDynamicSharedMemorySize, smem);

    wsplit_kernel<<<64, 256>>>(W2, W1);
    fused_kernel<<<B_, 256, smem>>>(state, action, Wk, Wq, Wv,
                                    b1, b2, Wout, bout, out);
}

// round 14
// speedup vs baseline: 1.0268x; 1.0268x over previous
#include <cuda_runtime.h>
#include <cuda_fp16.h>
#include <cstdint>

typedef unsigned long long u64;

namespace {
constexpr int B_ = 256, T_ = 128, SD_ = 8, AD_ = 2, H_ = 3, K_ = 4, HID_ = 256;
constexpr int QD_ = SD_ + AD_;    // 10
constexpr int HK_ = H_ * K_;      // 12
constexpr int FEAT_ = HK_ + QD_;  // 22
constexpr int MT_ = 128;          // tokens per CTA = one batch
constexpr int KP_ = 64;           // main-GEMM K panel
constexpr int ASTRIDE = 264;      // fp16 elems per A row (256 + 8 pad) -> 528B
}

// ---------------- helpers ----------------
__device__ __forceinline__ uint32_t smem_u32(const void* p) {
    uint32_t a;
    asm("{ .reg .u64 t; cvta.to.shared.u64 t, %1; cvt.u32.u64 %0, t; }" : "=r"(a) : "l"(p));
    return a;
}
__device__ __forceinline__ void ldsm4(uint32_t r[4], uint32_t addr) {
    asm volatile("ldmatrix.sync.aligned.m8n8.x4.shared.b16 {%0,%1,%2,%3}, [%4];"
                 : "=r"(r[0]), "=r"(r[1]), "=r"(r[2]), "=r"(r[3]) : "r"(addr));
}
__device__ __forceinline__ void mma16816(float c[4], const uint32_t a[4],
                                         uint32_t b0, uint32_t b1) {
    asm volatile(
        "mma.sync.aligned.m16n8k16.row.col.f32.f16.f16.f32 "
        "{%0,%1,%2,%3}, {%4,%5,%6,%7}, {%8,%9}, {%0,%1,%2,%3};"
        : "+f"(c[0]), "+f"(c[1]), "+f"(c[2]), "+f"(c[3])
        : "r"(a[0]), "r"(a[1]), "r"(a[2]), "r"(a[3]), "r"(b0), "r"(b1));
}
__device__ __forceinline__ uint32_t packh2(float lo, float hi) {
    __half2 h = __floats2half2_rn(lo, hi);
    return *(uint32_t*)&h;
}

// ---------------------------------------------------------------------------
// Fused kernel (single launch): one CTA = one batch (128 tokens), 256 thr.
//   prologue: LDG fp32 W2 panels 0,1 -> fp16 -> swizzled smem (convert
//             in-kernel: no prep kernel); W1 converted likewise.
//   phase 0: attention (2-way jj split), feat written as single fp16 tile.
//   phase 1: h1 via HMMA (single term, K=32), relu(D+b1) -> fp16 -> A tile.
//   phase 2: main HMMA D = A @ fp16(W2)^T, 4 K-panels of 64; panels 2,3
//            staged (LDG+cvt+STS) after consuming panels 0,1.
//   epilogue: h2 = D + b2; relu; dot Wout; reduce; +bout.
//   smem 161 KB -> preserves ~67 KB L1D (round-13 lesson).
// ---------------------------------------------------------------------------
__global__ __launch_bounds__(256) void fused_kernel(
    const float* __restrict__ state, const float* __restrict__ action,
    const float* __restrict__ Wk, const float* __restrict__ Wq,
    const float* __restrict__ Wv,
    const float* __restrict__ W1, const float* __restrict__ b1,
    const float* __restrict__ W2, const float* __restrict__ b2,
    const float* __restrict__ Wout, const float* __restrict__ bout,
    float* __restrict__ out)
{
    extern __shared__ char smem[];
    constexpr int ABYTES = MT_ * ASTRIDE * 2;          // 67584
    constexpr int OFF_A  = 0;
    constexpr int OFF_B  = ABYTES;                     // 2 bufs x 32768
    constexpr int BPANEL = HID_ * KP_ * 2;             // 32768
    constexpr int OFF_W1T = OFF_B + 2 * BPANEL;        // 16384 (fp16)
    constexpr int OFF_FH  = OFF_W1T + 16384;           // feat [128][64B] = 8192
    constexpr int OFF_BW  = OFF_FH + 8192;             // float2 x 256 = 2048
    constexpr int OFF_B1  = OFF_BW + 2048;             // float x 256
    constexpr int OFF_RED = OFF_B1 + 1024;             // float x 128
    // aliases inside A region (dead until phase 1 writes A)
    constexpr int OFF_SK = 0, OFF_SV = 6144, OFF_PART = 12288;

    const uint32_t sb = smem_u32(smem);
    const int tid = threadIdx.x, wid = tid >> 5, ln = tid & 31;
    const int b = blockIdx.x;

    float2* sBW = (float2*)(smem + OFF_BW);
    float* sB1 = (float*)(smem + OFF_B1);
    float* sred = (float*)(smem + OFF_RED);
    float (*sK)[HK_] = (float(*)[HK_])(smem + OFF_SK);
    float (*sV)[HK_] = (float(*)[HK_])(smem + OFF_SV);
    float (*sPA)[MT_] = (float(*)[MT_])(smem + OFF_PART);

    // ---- B panel staging: LDG fp32 -> fp16 -> swizzled STS ----
    const int srow0 = tid >> 3, sc = tid & 7;
    const int scx = (sc ^ (srow0 & 7)) << 4;           // row&7 constant across j
    auto stageB = [&](int p, int buf) {
        const uint32_t dbase = sb + OFF_B + (uint32_t)(buf * BPANEL + scx);
        const float* src = W2 + srow0 * HID_ + p * KP_ + sc * 8;
#pragma unroll
        for (int j = 0; j < 8; j++) {
            const float4 a4 = *(const float4*)(src + j * 32 * HID_);
            const float4 b4 = *(const float4*)(src + j * 32 * HID_ + 4);
            uint4 v;
            v.x = packh2(a4.x, a4.y);
            v.y = packh2(a4.z, a4.w);
            v.z = packh2(b4.x, b4.y);
            v.w = packh2(b4.z, b4.w);
            *(uint4*)(smem + (dbase - sb) + (uint32_t)((srow0 + j * 32) * 128)) = v;
        }
    };
    stageB(0, 0);
    stageB(1, 1);

    // ---- W1 convert: row tid (22 fp32 -> 32 fp16, zero pad), swizzled ----
    {
        const float2* w1row = (const float2*)(W1 + tid * FEAT_);  // 8B aligned
        uint32_t h[16];
#pragma unroll
        for (int i = 0; i < 11; i++) {
            const float2 w = w1row[i];
            h[i] = packh2(w.x, w.y);
        }
#pragma unroll
        for (int i = 11; i < 16; i++) h[i] = 0u;
#pragma unroll
        for (int c = 0; c < 4; c++) {
            uint4 v = make_uint4(h[4 * c], h[4 * c + 1], h[4 * c + 2], h[4 * c + 3]);
            *(uint4*)(smem + OFF_W1T + tid * 64 + ((c ^ ((tid >> 1) & 3)) << 4)) = v;
        }
    }

    // zero feat tile (pad cols 22..31 stay 0): 8192 B = 512 float4
    {
        float4* z = (float4*)(smem + OFF_FH);
#pragma unroll
        for (int i = 0; i < 2; i++) z[tid + i * 256] = make_float4(0.f, 0.f, 0.f, 0.f);
    }
    sBW[tid] = make_float2(b2[tid], Wout[tid]);
    sB1[tid] = b1[tid];
    if (tid < MT_) sred[tid] = 0.f;

    // ---- phase 0: attention ----
    const int half = tid >> 7, t = tid & 127;
    float qs[QD_], q[HK_], kp[HK_], vp[HK_];
    {
        const float* st = state + (size_t)(b * T_ + t) * SD_;
        const float* ac = action + (size_t)(b * T_ + t) * AD_;
#pragma unroll
        for (int c = 0; c < SD_; c++) qs[c] = st[c];
        qs[SD_] = ac[0];
        qs[SD_ + 1] = ac[1];
#pragma unroll
        for (int i = 0; i < HK_; i++) {
            float a = 0.f;
#pragma unroll
            for (int c = 0; c < QD_; c++) a = fmaf(qs[c], Wq[i * QD_ + c], a);
            q[i] = a;
        }
#pragma unroll
        for (int i = 0; i < HK_; i++) {
            float ak = 0.f, av = 0.f;
#pragma unroll
            for (int c = 0; c < K_; c++) {
                ak = fmaf(qs[c], Wk[i * K_ + c], ak);
                av = fmaf(qs[c], Wv[i * K_ + c], av);
            }
            kp[i] = ak; vp[i] = av;
        }
        if (half == 0) {
#pragma unroll
            for (int i = 0; i < HK_; i++) { sK[t][i] = kp[i]; sV[t][i] = vp[i]; }
        }
    }
    __syncthreads();

    {
        float sum0 = 0.f, sum1 = 0.f, sum2 = 0.f;
        float acc[HK_];
#pragma unroll
        for (int i = 0; i < HK_; i++) acc[i] = 0.f;
        const int j0 = half * 64;
#pragma unroll 4
        for (int jx = 0; jx < 64; jx++) {
            const int jj = j0 + jx;
            const float4 k0 = *(const float4*)&sK[jj][0];
            const float4 k1 = *(const float4*)&sK[jj][4];
            const float4 k2 = *(const float4*)&sK[jj][8];
            float s0 = q[0]*k0.x + q[1]*k0.y + q[2]*k0.z + q[3]*k0.w;
            float s1 = q[4]*k1.x + q[5]*k1.y + q[6]*k1.z + q[7]*k1.w;
            float s2 = q[8]*k2.x + q[9]*k2.y + q[10]*k2.z + q[11]*k2.w;
            const float e0 = __expf(0.5f * s0);
            const float e1 = __expf(0.5f * s1);
            const float e2 = __expf(0.5f * s2);
            sum0 += e0; sum1 += e1; sum2 += e2;
            const float4 v0 = *(const float4*)&sV[jj][0];
            const float4 v1 = *(const float4*)&sV[jj][4];
            const float4 v2 = *(const float4*)&sV[jj][8];
            acc[0]  = fmaf(e0, v0.x, acc[0]);  acc[1]  = fmaf(e0, v0.y, acc[1]);
            acc[2]  = fmaf(e0, v0.z, acc[2]);  acc[3]  = fmaf(e0, v0.w, acc[3]);
            acc[4]  = fmaf(e1, v1.x, acc[4]);  acc[5]  = fmaf(e1, v1.y, acc[5]);
            acc[6]  = fmaf(e1, v1.z, acc[6]);  acc[7]  = fmaf(e1, v1.w, acc[7]);
            acc[8]  = fmaf(e2, v2.x, acc[8]);  acc[9]  = fmaf(e2, v2.y, acc[9]);
            acc[10] = fmaf(e2, v2.z, acc[10]); acc[11] = fmaf(e2, v2.w, acc[11]);
        }
        if (half == 1) {
            sPA[0][t] = sum0; sPA[1][t] = sum1; sPA[2][t] = sum2;
#pragma unroll
            for (int i = 0; i < HK_; i++) sPA[3 + i][t] = acc[i];
        }
        __syncthreads();
        if (half == 0) {
            sum0 += sPA[0][t]; sum1 += sPA[1][t]; sum2 += sPA[2][t];
#pragma unroll
            for (int i = 0; i < HK_; i++) acc[i] += sPA[3 + i][t];
            float s0 = q[0]*kp[0] + q[1]*kp[1] + q[2]*kp[2] + q[3]*kp[3];
            float s1 = q[4]*kp[4] + q[5]*kp[5] + q[6]*kp[6] + q[7]*kp[7];
            float s2 = q[8]*kp[8] + q[9]*kp[9] + q[10]*kp[10] + q[11]*kp[11];
            const float e0 = __expf(0.5f * s0);
            const float e1 = __expf(0.5f * s1);
            const float e2 = __expf(0.5f * s2);
            sum0 -= e0; sum1 -= e1; sum2 -= e2;
            const float i0 = 1.f / sum0, i1 = 1.f / sum1, i2 = 1.f / sum2;
            float f[FEAT_];
#pragma unroll
            for (int k = 0; k < K_; k++) {
                f[k]     = fmaf(-e0, vp[k],     acc[k])     * i0 - vp[k];
                f[4 + k] = fmaf(-e1, vp[4 + k], acc[4 + k]) * i1 - vp[4 + k];
                f[8 + k] = fmaf(-e2, vp[8 + k], acc[8 + k]) * i2 - vp[8 + k];
            }
#pragma unroll
            for (int c = 0; c < QD_; c++) f[HK_ + c] = qs[c];
            // write feat as single fp16 into swizzled [128][32] tile
#pragma unroll
            for (int c = 0; c < FEAT_; c++) {
                const uint32_t ad = (uint32_t)(t * 64 + (((c >> 3) ^ ((t >> 1) & 3)) << 4) +
                                               (c & 7) * 2);
                *(__half*)(smem + OFF_FH + ad) = __float2half_rn(f[c]);
            }
        }
    }
    __syncthreads();

    // ---- warp tiling: 2(M) x 4(N), warp tile 64x64 ----
    const int mwarp = wid >> 2, nwarp = wid & 3;
    const int m0w = mwarp * 64, n0w = nwarp * 64;
    const int rsel = (ln & 7) | (((ln >> 4) & 1) << 3);
    const int cpart = (ln >> 3) & 1;

    float acc[4][8][4];
#pragma unroll
    for (int i = 0; i < 4; i++)
#pragma unroll
        for (int j = 0; j < 8; j++)
#pragma unroll
            for (int c = 0; c < 4; c++) acc[i][j][c] = 0.f;

    // ---- phase 1: W1 HMMA (single term, K=32) ----
    {
        const int aRow = m0w + (ln & 15);
        const int aSw = (aRow >> 1) & 3;
        const int aCS = ln >> 4;
        const int bSw = (rsel >> 1) & 3;
#pragma unroll
        for (int ks = 0; ks < 2; ks++) {
            uint32_t ah[4][4], bh[4][4];
#pragma unroll
            for (int i = 0; i < 4; i++)
                ldsm4(ah[i], sb + OFF_FH + (uint32_t)((aRow + i * 16) * 64 +
                              (((ks * 2 + aCS) ^ aSw) << 4)));
#pragma unroll
            for (int j = 0; j < 4; j++)
                ldsm4(bh[j], sb + OFF_W1T + (uint32_t)((n0w + j * 16 + rsel) * 64 +
                              (((ks * 2 + cpart) ^ bSw) << 4)));
#pragma unroll
            for (int j = 0; j < 4; j++)
#pragma unroll
                for (int i = 0; i < 4; i++) {
                    mma16816(acc[i][2 * j],     ah[i], bh[j][0], bh[j][1]);
                    mma16816(acc[i][2 * j + 1], ah[i], bh[j][2], bh[j][3]);
                }
        }
        // h1 = relu(D + b1) -> fp16 -> main A tile (row-major, padded stride)
#pragma unroll
        for (int i = 0; i < 4; i++) {
            const int r0 = m0w + i * 16 + (ln >> 2);
#pragma unroll
            for (int j = 0; j < 8; j++) {
                const int n = n0w + j * 8 + 2 * (ln & 3);
                const float h0 = fmaxf(acc[i][j][0] + sB1[n], 0.f);
                const float h1v = fmaxf(acc[i][j][1] + sB1[n + 1], 0.f);
                const float h2 = fmaxf(acc[i][j][2] + sB1[n], 0.f);
                const float h3 = fmaxf(acc[i][j][3] + sB1[n + 1], 0.f);
                *(uint32_t*)(smem + OFF_A + r0 * (ASTRIDE * 2) + n * 2) = packh2(h0, h1v);
                *(uint32_t*)(smem + OFF_A + (r0 + 8) * (ASTRIDE * 2) + n * 2) = packh2(h2, h3);
            }
        }
    }
    __syncthreads();

    // ---- phase 2: main HMMA GEMM, 4 K-panels; panels 2,3 staged in-loop ----
#pragma unroll
    for (int i = 0; i < 4; i++)
#pragma unroll
        for (int j = 0; j < 8; j++)
#pragma unroll
            for (int c = 0; c < 4; c++) acc[i][j][c] = 0.f;

    const uint32_t aBase = sb + OFF_A +
        (uint32_t)((m0w + (ln & 15)) * (ASTRIDE * 2) + (ln >> 4) * 16);
    const int swz = ln & 7;
    const uint32_t bRow = (uint32_t)((n0w + rsel) * 128);

#pragma unroll
    for (int p = 0; p < 4; p++) {
        const uint32_t bBase = sb + OFF_B + (uint32_t)((p & 1) * BPANEL) + bRow;

#pragma unroll
        for (int ks = 0; ks < 4; ks++) {
            uint32_t ah[4][4], bh[4][4];
            const uint32_t ka = (uint32_t)(p * 128 + ks * 32);
#pragma unroll
            for (int i = 0; i < 4; i++)
                ldsm4(ah[i], aBase + ka + (uint32_t)(i * 16 * ASTRIDE * 2));
            const uint32_t bchunk = (uint32_t)(((ks * 2 + cpart) ^ swz) << 4);
#pragma unroll
            for (int jj = 0; jj < 4; jj++)
                ldsm4(bh[jj], bBase + bchunk + (uint32_t)(jj * 16 * 128));
#pragma unroll
            for (int jj = 0; jj < 4; jj++)
#pragma unroll
                for (int i = 0; i < 4; i++) {
                    mma16816(acc[i][2 * jj],     ah[i], bh[jj][0], bh[jj][1]);
                    mma16816(acc[i][2 * jj + 1], ah[i], bh[jj][2], bh[jj][3]);
                }
        }
        if (p < 3) __syncthreads();         // buffer (p&1) fully consumed CTA-wide
        if (p < 2) stageB(p + 2, p & 1);    // refill it; next iter MMAs other buf
        // stage(p+2) -> consumed at iter p+2; iter p+1's post-MMA sync orders it
    }

    // ---- epilogue: h2 = acc + b2; relu; dot Wout; reduce ----
    float po[4][2] = {{0.f, 0.f}, {0.f, 0.f}, {0.f, 0.f}, {0.f, 0.f}};
#pragma unroll
    for (int i = 0; i < 4; i++)
#pragma unroll
        for (int j = 0; j < 8; j++) {
            const int nb = n0w + j * 8 + 2 * (ln & 3);
            const float2 bw0 = sBW[nb], bw1 = sBW[nb + 1];
            po[i][0] += fmaxf(acc[i][j][0] + bw0.x, 0.f) * bw0.y
                      + fmaxf(acc[i][j][1] + bw1.x, 0.f) * bw1.y;
            po[i][1] += fmaxf(acc[i][j][2] + bw0.x, 0.f) * bw0.y
                      + fmaxf(acc[i][j][3] + bw1.x, 0.f) * bw1.y;
        }
#pragma unroll
    for (int o = 1; o <= 2; o <<= 1)
#pragma unroll
        for (int i = 0; i < 4; i++) {
            po[i][0] += __shfl_xor_sync(0xffffffffu, po[i][0], o);
            po[i][1] += __shfl_xor_sync(0xffffffffu, po[i][1], o);
        }
    if ((ln & 3) == 0) {
        const int r = ln >> 2;
#pragma unroll
        for (int i = 0; i < 4; i++) {
            atomicAdd(&sred[m0w + i * 16 + r], po[i][0]);
            atomicAdd(&sred[m0w + i * 16 + 8 + r], po[i][1]);
        }
    }
    __syncthreads();
    if (tid < MT_) out[b * T_ + tid] = sred[tid] + bout[0];
}

extern "C" void kernel_launch(void* const* d_in, const int* in_sizes, int n_in,
                              void* d_out, int out_size) {
    const float* state  = (const float*)d_in[0];
    const float* action = (const float*)d_in[1];
    const float* Wk     = (const float*)d_in[2];
    const float* Wq     = (const float*)d_in[3];
    const float* Wv     = (const float*)d_in[4];
    const float* W1     = (const float*)d_in[5];
    const float* b1     = (const float*)d_in[6];
    const float* W2     = (const float*)d_in[7];
    const float* b2     = (const float*)d_in[8];
    const float* Wout   = (const float*)d_in[9];
    const float* bout   = (const float*)d_in[10];
    float* out = (float*)d_out;

    const int smem = MT_ * ASTRIDE * 2          // A tile          67584
                   + 2 * (HID_ * KP_ * 2)       // B double buffer 65536
                   + 16384                      // W1 tile (fp16)
                   + 8192                       // feat tile (fp16)
                   + 2048 + 1024 + 512;         // bw, b1, red     -> 161280
    cudaFuncSetAttribute(fused_kernel, cudaFuncAttributeMaxDynamicSharedMemorySize, smem);

    fused_kernel<<<B_, 256, smem>>>(state, action, Wk, Wq, Wv,
                                    W1, b1, W2, b2, Wout, bout, out);
}

// round 15
// speedup vs baseline: 1.1123x; 1.0833x over previous
#include <cuda_runtime.h>
#include <cuda_fp16.h>
#include <cstdint>

typedef unsigned long long u64;

namespace {
constexpr int B_ = 256, T_ = 128, SD_ = 8, AD_ = 2, H_ = 3, K_ = 4, HID_ = 256;
constexpr int QD_ = SD_ + AD_;    // 10
constexpr int HK_ = H_ * K_;      // 12
constexpr int FEAT_ = HK_ + QD_;  // 22
constexpr int MT_ = 128;          // tokens per CTA = one batch
constexpr int KP_ = 64;           // main-GEMM K panel
constexpr int ASTRIDE = 264;      // fp16 elems per A row (256 + 8 pad) -> 528B
}

// fp16(W2), produced by wsplit_kernel, consumed after griddepcontrol.wait
__device__ __half g_W2h[HID_ * HID_];

// ---------------- helpers ----------------
__device__ __forceinline__ uint32_t smem_u32(const void* p) {
    uint32_t a;
    asm("{ .reg .u64 t; cvta.to.shared.u64 t, %1; cvt.u32.u64 %0, t; }" : "=r"(a) : "l"(p));
    return a;
}
__device__ __forceinline__ void ldsm4(uint32_t r[4], uint32_t addr) {
    asm volatile("ldmatrix.sync.aligned.m8n8.x4.shared.b16 {%0,%1,%2,%3}, [%4];"
                 : "=r"(r[0]), "=r"(r[1]), "=r"(r[2]), "=r"(r[3]) : "r"(addr));
}
__device__ __forceinline__ void mma16816(float c[4], const uint32_t a[4],
                                         uint32_t b0, uint32_t b1) {
    asm volatile(
        "mma.sync.aligned.m16n8k16.row.col.f32.f16.f16.f32 "
        "{%0,%1,%2,%3}, {%4,%5,%6,%7}, {%8,%9}, {%0,%1,%2,%3};"
        : "+f"(c[0]), "+f"(c[1]), "+f"(c[2]), "+f"(c[3])
        : "r"(a[0]), "r"(a[1]), "r"(a[2]), "r"(a[3]), "r"(b0), "r"(b1));
}
__device__ __forceinline__ void cp_async16(uint32_t dst, const void* src) {
    asm volatile("cp.async.ca.shared.global [%0], [%1], 16;" :: "r"(dst), "l"(src) : "memory");
}
__device__ __forceinline__ uint32_t packh2(float lo, float hi) {
    __half2 h = __floats2half2_rn(lo, hi);
    return *(uint32_t*)&h;
}

// ---------------------------------------------------------------------------
// Prep (overlapped via PDL): W2 -> fp16, float4-vectorized, grid 64.
// ---------------------------------------------------------------------------
__global__ __launch_bounds__(256) void wsplit_kernel(const float* __restrict__ W2) {
    const int gid = blockIdx.x * 256 + threadIdx.x;   // 16384 threads
    const float4 w4 = ((const float4*)W2)[gid];
    ((__half2*)g_W2h)[gid * 2]     = __floats2half2_rn(w4.x, w4.y);
    ((__half2*)g_W2h)[gid * 2 + 1] = __floats2half2_rn(w4.z, w4.w);
}

// ---------------------------------------------------------------------------
// Fused kernel: one CTA = one batch (128 tokens), 256 threads, 8 warps.
//   prologue: W1 converted fp32->fp16 in-kernel (no W2 dependency).
//   phase 0: attention (2-way jj split), feat written as single fp16 tile.
//   --- griddepcontrol.wait (PDL): g_W2h now valid ---
//   phase 1: h1 via HMMA (single term, K=32), relu(D+b1) -> fp16 -> A tile;
//            B panel 0 cp.async'd underneath.
//   phase 2: main HMMA D = A @ fp16(W2)^T, 4 K-panels of 64, double-buffered
//            cp.async (round-11 ledger).
//   epilogue: h2 = D + b2; relu; dot Wout; reduce; +bout.
//   smem 161 KB -> preserves ~67 KB L1D.
// ---------------------------------------------------------------------------
__global__ __launch_bounds__(256) void fused_kernel(
    const float* __restrict__ state, const float* __restrict__ action,
    const float* __restrict__ Wk, const float* __restrict__ Wq,
    const float* __restrict__ Wv,
    const float* __restrict__ W1, const float* __restrict__ b1,
    const float* __restrict__ b2, const float* __restrict__ Wout,
    const float* __restrict__ bout, float* __restrict__ out)
{
    extern __shared__ char smem[];
    constexpr int ABYTES = MT_ * ASTRIDE * 2;          // 67584
    constexpr int OFF_A  = 0;
    constexpr int OFF_B  = ABYTES;                     // 2 bufs x 32768
    constexpr int BPANEL = HID_ * KP_ * 2;             // 32768
    constexpr int OFF_W1T = OFF_B + 2 * BPANEL;        // 16384 (fp16)
    constexpr int OFF_FH  = OFF_W1T + 16384;           // feat [128][64B] = 8192
    constexpr int OFF_BW  = OFF_FH + 8192;             // float2 x 256 = 2048
    constexpr int OFF_B1  = OFF_BW + 2048;             // float x 256
    constexpr int OFF_RED = OFF_B1 + 1024;             // float x 128
    // aliases inside A region (dead until phase 1 writes A)
    constexpr int OFF_SK = 0, OFF_SV = 6144, OFF_PART = 12288;

    const uint32_t sb = smem_u32(smem);
    const int tid = threadIdx.x, wid = tid >> 5, ln = tid & 31;
    const int b = blockIdx.x;

    float2* sBW = (float2*)(smem + OFF_BW);
    float* sB1 = (float*)(smem + OFF_B1);
    float* sred = (float*)(smem + OFF_RED);
    float (*sK)[HK_] = (float(*)[HK_])(smem + OFF_SK);
    float (*sV)[HK_] = (float(*)[HK_])(smem + OFF_SV);
    float (*sPA)[MT_] = (float(*)[MT_])(smem + OFF_PART);

    // ---- B panel staging from g_W2h (cp.async; valid only post-gridsync) ----
    const int srow0 = tid >> 3, sc = tid & 7;
    const int scx = (sc ^ (srow0 & 7)) << 4;           // row&7 constant across j
    auto stageB = [&](int p, int buf) {
        const uint32_t dbase = sb + OFF_B + (uint32_t)(buf * BPANEL + scx);
        const int goff = srow0 * HID_ + p * KP_ + sc * 8;
#pragma unroll
        for (int j = 0; j < 8; j++) {
            cp_async16(dbase + (uint32_t)((srow0 + j * 32) * 128),
                       g_W2h + goff + j * 32 * HID_);
        }
        asm volatile("cp.async.commit_group;" ::: "memory");
    };

    // ---- prologue: W1 convert (fp32 -> fp16, K pad 22->32), swizzled ----
    {
        const float2* w1row = (const float2*)(W1 + tid * FEAT_);  // 8B aligned
        uint32_t h[16];
#pragma unroll
        for (int i = 0; i < 11; i++) {
            const float2 w = w1row[i];
            h[i] = packh2(w.x, w.y);
        }
#pragma unroll
        for (int i = 11; i < 16; i++) h[i] = 0u;
#pragma unroll
        for (int c = 0; c < 4; c++) {
            uint4 v = make_uint4(h[4 * c], h[4 * c + 1], h[4 * c + 2], h[4 * c + 3]);
            *(uint4*)(smem + OFF_W1T + tid * 64 + ((c ^ ((tid >> 1) & 3)) << 4)) = v;
        }
    }
    // zero feat tile (pad cols 22..31 stay 0): 8192 B = 512 float4
    {
        float4* z = (float4*)(smem + OFF_FH);
#pragma unroll
        for (int i = 0; i < 2; i++) z[tid + i * 256] = make_float4(0.f, 0.f, 0.f, 0.f);
    }
    sBW[tid] = make_float2(b2[tid], Wout[tid]);
    sB1[tid] = b1[tid];
    if (tid < MT_) sred[tid] = 0.f;

    // ---- phase 0: attention ----
    const int half = tid >> 7, t = tid & 127;
    float qs[QD_], q[HK_], kp[HK_], vp[HK_];
    {
        const float* st = state + (size_t)(b * T_ + t) * SD_;
        const float* ac = action + (size_t)(b * T_ + t) * AD_;
#pragma unroll
        for (int c = 0; c < SD_; c++) qs[c] = st[c];
        qs[SD_] = ac[0];
        qs[SD_ + 1] = ac[1];
#pragma unroll
        for (int i = 0; i < HK_; i++) {
            float a = 0.f;
#pragma unroll
            for (int c = 0; c < QD_; c++) a = fmaf(qs[c], Wq[i * QD_ + c], a);
            q[i] = a;
        }
#pragma unroll
        for (int i = 0; i < HK_; i++) {
            float ak = 0.f, av = 0.f;
#pragma unroll
            for (int c = 0; c < K_; c++) {
                ak = fmaf(qs[c], Wk[i * K_ + c], ak);
                av = fmaf(qs[c], Wv[i * K_ + c], av);
            }
            kp[i] = ak; vp[i] = av;
        }
        if (half == 0) {
#pragma unroll
            for (int i = 0; i < HK_; i++) { sK[t][i] = kp[i]; sV[t][i] = vp[i]; }
        }
    }
    __syncthreads();

    {
        float sum0 = 0.f, sum1 = 0.f, sum2 = 0.f;
        float acc[HK_];
#pragma unroll
        for (int i = 0; i < HK_; i++) acc[i] = 0.f;
        const int j0 = half * 64;
#pragma unroll 4
        for (int jx = 0; jx < 64; jx++) {
            const int jj = j0 + jx;
            const float4 k0 = *(const float4*)&sK[jj][0];
            const float4 k1 = *(const float4*)&sK[jj][4];
            const float4 k2 = *(const float4*)&sK[jj][8];
            float s0 = q[0]*k0.x + q[1]*k0.y + q[2]*k0.z + q[3]*k0.w;
            float s1 = q[4]*k1.x + q[5]*k1.y + q[6]*k1.z + q[7]*k1.w;
            float s2 = q[8]*k2.x + q[9]*k2.y + q[10]*k2.z + q[11]*k2.w;
            const float e0 = __expf(0.5f * s0);
            const float e1 = __expf(0.5f * s1);
            const float e2 = __expf(0.5f * s2);
            sum0 += e0; sum1 += e1; sum2 += e2;
            const float4 v0 = *(const float4*)&sV[jj][0];
            const float4 v1 = *(const float4*)&sV[jj][4];
            const float4 v2 = *(const float4*)&sV[jj][8];
            acc[0]  = fmaf(e0, v0.x, acc[0]);  acc[1]  = fmaf(e0, v0.y, acc[1]);
            acc[2]  = fmaf(e0, v0.z, acc[2]);  acc[3]  = fmaf(e0, v0.w, acc[3]);
            acc[4]  = fmaf(e1, v1.x, acc[4]);  acc[5]  = fmaf(e1, v1.y, acc[5]);
            acc[6]  = fmaf(e1, v1.z, acc[6]);  acc[7]  = fmaf(e1, v1.w, acc[7]);
            acc[8]  = fmaf(e2, v2.x, acc[8]);  acc[9]  = fmaf(e2, v2.y, acc[9]);
            acc[10] = fmaf(e2, v2.z, acc[10]); acc[11] = fmaf(e2, v2.w, acc[11]);
        }
        if (half == 1) {
            sPA[0][t] = sum0; sPA[1][t] = sum1; sPA[2][t] = sum2;
#pragma unroll
            for (int i = 0; i < HK_; i++) sPA[3 + i][t] = acc[i];
        }
        __syncthreads();
        if (half == 0) {
            sum0 += sPA[0][t]; sum1 += sPA[1][t]; sum2 += sPA[2][t];
#pragma unroll
            for (int i = 0; i < HK_; i++) acc[i] += sPA[3 + i][t];
            float s0 = q[0]*kp[0] + q[1]*kp[1] + q[2]*kp[2] + q[3]*kp[3];
            float s1 = q[4]*kp[4] + q[5]*kp[5] + q[6]*kp[6] + q[7]*kp[7];
            float s2 = q[8]*kp[8] + q[9]*kp[9] + q[10]*kp[10] + q[11]*kp[11];
            const float e0 = __expf(0.5f * s0);
            const float e1 = __expf(0.5f * s1);
            const float e2 = __expf(0.5f * s2);
            sum0 -= e0; sum1 -= e1; sum2 -= e2;
            const float i0 = 1.f / sum0, i1 = 1.f / sum1, i2 = 1.f / sum2;
            float f[FEAT_];
#pragma unroll
            for (int k = 0; k < K_; k++) {
                f[k]     = fmaf(-e0, vp[k],     acc[k])     * i0 - vp[k];
                f[4 + k] = fmaf(-e1, vp[4 + k], acc[4 + k]) * i1 - vp[4 + k];
                f[8 + k] = fmaf(-e2, vp[8 + k], acc[8 + k]) * i2 - vp[8 + k];
            }
#pragma unroll
            for (int c = 0; c < QD_; c++) f[HK_ + c] = qs[c];
            // write feat as single fp16 into swizzled [128][32] tile
#pragma unroll
            for (int c = 0; c < FEAT_; c++) {
                const uint32_t ad = (uint32_t)(t * 64 + (((c >> 3) ^ ((t >> 1) & 3)) << 4) +
                                               (c & 7) * 2);
                *(__half*)(smem + OFF_FH + ad) = __float2half_rn(f[c]);
            }
        }
    }

    // ---- PDL sync: wsplit's g_W2h writes are now visible; start B staging ----
    asm volatile("griddepcontrol.wait;" ::: "memory");
    stageB(0, 0);
    __syncthreads();   // feat + W1 tiles ready for phase 1 (panel 0 in flight)

    // ---- warp tiling: 2(M) x 4(N), warp tile 64x64 ----
    const int mwarp = wid >> 2, nwarp = wid & 3;
    const int m0w = mwarp * 64, n0w = nwarp * 64;
    const int rsel = (ln & 7) | (((ln >> 4) & 1) << 3);
    const int cpart = (ln >> 3) & 1;

    float acc[4][8][4];
#pragma unroll
    for (int i = 0; i < 4; i++)
#pragma unroll
        for (int j = 0; j < 8; j++)
#pragma unroll
            for (int c = 0; c < 4; c++) acc[i][j][c] = 0.f;

    // ---- phase 1: W1 HMMA (single term, K=32) ----
    {
        const int aRow = m0w + (ln & 15);
        const int aSw = (aRow >> 1) & 3;
        const int aCS = ln >> 4;
        const int bSw = (rsel >> 1) & 3;
#pragma unroll
        for (int ks = 0; ks < 2; ks++) {
            uint32_t ah[4][4], bh[4][4];
#pragma unroll
            for (int i = 0; i < 4; i++)
                ldsm4(ah[i], sb + OFF_FH + (uint32_t)((aRow + i * 16) * 64 +
                              (((ks * 2 + aCS) ^ aSw) << 4)));
#pragma unroll
            for (int j = 0; j < 4; j++)
                ldsm4(bh[j], sb + OFF_W1T + (uint32_t)((n0w + j * 16 + rsel) * 64 +
                              (((ks * 2 + cpart) ^ bSw) << 4)));
#pragma unroll
            for (int j = 0; j < 4; j++)
#pragma unroll
                for (int i = 0; i < 4; i++) {
                    mma16816(acc[i][2 * j],     ah[i], bh[j][0], bh[j][1]);
                    mma16816(acc[i][2 * j + 1], ah[i], bh[j][2], bh[j][3]);
                }
        }
        // h1 = relu(D + b1) -> fp16 -> main A tile (row-major, padded stride)
#pragma unroll
        for (int i = 0; i < 4; i++) {
            const int r0 = m0w + i * 16 + (ln >> 2);
#pragma unroll
            for (int j = 0; j < 8; j++) {
                const int n = n0w + j * 8 + 2 * (ln & 3);
                const float h0 = fmaxf(acc[i][j][0] + sB1[n], 0.f);
                const float h1v = fmaxf(acc[i][j][1] + sB1[n + 1], 0.f);
                const float h2 = fmaxf(acc[i][j][2] + sB1[n], 0.f);
                const float h3 = fmaxf(acc[i][j][3] + sB1[n + 1], 0.f);
                *(uint32_t*)(smem + OFF_A + r0 * (ASTRIDE * 2) + n * 2) = packh2(h0, h1v);
                *(uint32_t*)(smem + OFF_A + (r0 + 8) * (ASTRIDE * 2) + n * 2) = packh2(h2, h3);
            }
        }
    }
    __syncthreads();

    // ---- phase 2: main HMMA GEMM, 4 K-panels, double-buffered (R11 ledger) ----
#pragma unroll
    for (int i = 0; i < 4; i++)
#pragma unroll
        for (int j = 0; j < 8; j++)
#pragma unroll
            for (int c = 0; c < 4; c++) acc[i][j][c] = 0.f;

    const uint32_t aBase = sb + OFF_A +
        (uint32_t)((m0w + (ln & 15)) * (ASTRIDE * 2) + (ln >> 4) * 16);
    const int swz = ln & 7;
    const uint32_t bRow = (uint32_t)((n0w + rsel) * 128);

    for (int p = 0; p < 4; p++) {
        if (p < 3) {
            stageB(p + 1, (p + 1) & 1);
            asm volatile("cp.async.wait_group 1;" ::: "memory");
        } else {
            asm volatile("cp.async.wait_group 0;" ::: "memory");
        }
        __syncthreads();

        const uint32_t bBase = sb + OFF_B + (uint32_t)((p & 1) * BPANEL) + bRow;

#pragma unroll
        for (int ks = 0; ks < 4; ks++) {
            uint32_t ah[4][4], bh[4][4];
            const uint32_t ka = (uint32_t)(p * 128 + ks * 32);
#pragma unroll
            for (int i = 0; i < 4; i++)
                ldsm4(ah[i], aBase + ka + (uint32_t)(i * 16 * ASTRIDE * 2));
            const uint32_t bchunk = (uint32_t)(((ks * 2 + cpart) ^ swz) << 4);
#pragma unroll
            for (int jj = 0; jj < 4; jj++)
                ldsm4(bh[jj], bBase + bchunk + (uint32_t)(jj * 16 * 128));
#pragma unroll
            for (int jj = 0; jj < 4; jj++)
#pragma unroll
                for (int i = 0; i < 4; i++) {
                    mma16816(acc[i][2 * jj],     ah[i], bh[jj][0], bh[jj][1]);
                    mma16816(acc[i][2 * jj + 1], ah[i], bh[jj][2], bh[jj][3]);
                }
        }
        __syncthreads();
    }

    // ---- epilogue: h2 = acc + b2; relu; dot Wout; reduce ----
    float po[4][2] = {{0.f, 0.f}, {0.f, 0.f}, {0.f, 0.f}, {0.f, 0.f}};
#pragma unroll
    for (int i = 0; i < 4; i++)
#pragma unroll
        for (int j = 0; j < 8; j++) {
            const int nb = n0w + j * 8 + 2 * (ln & 3);
            const float2 bw0 = sBW[nb], bw1 = sBW[nb + 1];
            po[i][0] += fmaxf(acc[i][j][0] + bw0.x, 0.f) * bw0.y
                      + fmaxf(acc[i][j][1] + bw1.x, 0.f) * bw1.y;
            po[i][1] += fmaxf(acc[i][j][2] + bw0.x, 0.f) * bw0.y
                      + fmaxf(acc[i][j][3] + bw1.x, 0.f) * bw1.y;
        }
#pragma unroll
    for (int o = 1; o <= 2; o <<= 1)
#pragma unroll
        for (int i = 0; i < 4; i++) {
            po[i][0] += __shfl_xor_sync(0xffffffffu, po[i][0], o);
            po[i][1] += __shfl_xor_sync(0xffffffffu, po[i][1], o);
        }
    if ((ln & 3) == 0) {
        const int r = ln >> 2;
#pragma unroll
        for (int i = 0; i < 4; i++) {
            atomicAdd(&sred[m0w + i * 16 + r], po[i][0]);
            atomicAdd(&sred[m0w + i * 16 + 8 + r], po[i][1]);
        }
    }
    __syncthreads();
    if (tid < MT_) out[b * T_ + tid] = sred[tid] + bout[0];
}

extern "C" void kernel_launch(void* const* d_in, const int* in_sizes, int n_in,
                              void* d_out, int out_size) {
    const float* state  = (const float*)d_in[0];
    const float* action = (const float*)d_in[1];
    const float* Wk     = (const float*)d_in[2];
    const float* Wq     = (const float*)d_in[3];
    const float* Wv     = (const float*)d_in[4];
    const float* W1     = (const float*)d_in[5];
    const float* b1     = (const float*)d_in[6];
    const float* W2     = (const float*)d_in[7];
    const float* b2     = (const float*)d_in[8];
    const float* Wout   = (const float*)d_in[9];
    const float* bout   = (const float*)d_in[10];
    float* out = (float*)d_out;

    const int smem = MT_ * ASTRIDE * 2          // A tile          67584
                   + 2 * (HID_ * KP_ * 2)       // B double buffer 65536
                   + 16384                      // W1 tile (fp16)
                   + 8192                       // feat tile (fp16)
                   + 2048 + 1024 + 512;         // bw, b1, red     -> 161280
    cudaFuncSetAttribute(fused_kernel, cudaFuncAttributeMaxDynamicSharedMemorySize, smem);

    wsplit_kernel<<<64, 256>>>(W2);

    // fused kernel with programmatic dependent launch: overlaps with wsplit;
    // griddepcontrol.wait inside orders the g_W2h reads.
    cudaLaunchConfig_t cfg = {};
    cfg.gridDim = dim3(B_, 1, 1);
    cfg.blockDim = dim3(256, 1, 1);
    cfg.dynamicSmemBytes = (size_t)smem;
    cfg.stream = 0;
    cudaLaunchAttribute attrs[1];
    attrs[0].id = cudaLaunchAttributeProgrammaticStreamSerialization;
    attrs[0].val.programmaticStreamSerializationAllowed = 1;
    cfg.attrs = attrs;
    cfg.numAttrs = 1;
    cudaLaunchKernelEx(&cfg, fused_kernel, state, action, Wk, Wq, Wv,
                       W1, b1, b2, Wout, bout, out);
}